// round 11
// baseline (speedup 1.0000x reference)
#include <cuda_runtime.h>
#include <cuda_bf16.h>
#include <math.h>
#include <stdint.h>

#define B_    64
#define S_    4096
#define E_    266
#define HID_  512
#define NH_   128
#define M_    (B_ * NH_)   /* 8192 rows */
#define KC_   64           /* K chunk */
#define NCH_  (HID_ / KC_) /* 8 chunks */
#define SPAD_ 72           /* padded smem row stride in bf16 (144B = 9x16B, ldsm conflict-free) */
#define BM_   256          /* CTA tile M */
#define BN_   128          /* CTA tile N */

#define ROWB_     (SPAD_ * 2)                       /* 144 B */
#define OFF_AH    0
#define OFF_AL    (BM_ * ROWB_)                     /* 36864 */
#define OFF_BH    (2 * BM_ * ROWB_)                 /* 73728 */
#define OFF_BL    (2 * BM_ * ROWB_ + BN_ * ROWB_)   /* 92160 */
#define STAGE_B   (2 * BM_ * ROWB_ + 2 * BN_ * ROWB_) /* 110592 */
#define NSTAGE_   2
#define SMEM_DYN  (NSTAGE_ * STAGE_B)               /* 221184 */

__device__ __align__(16) __nv_bfloat16 g_ahi[2][M_ * HID_];
__device__ __align__(16) __nv_bfloat16 g_alo[2][M_ * HID_];
__device__ __align__(16) __nv_bfloat16 g_wthi[3][HID_ * HID_];
__device__ __align__(16) __nv_bfloat16 g_wtlo[3][HID_ * HID_];
__device__ float g_zw[B_ * HID_];
__device__ float g_ew[NH_ * HID_];
__device__ float g_sinc[M_];
__device__ float g_cosc[M_];

__device__ __forceinline__ float silu(float v) {
    return __fdividef(v, 1.0f + __expf(-v));
}
__device__ __forceinline__ uint32_t smem_u32(const void* p) {
    uint32_t a;
    asm("{ .reg .u64 t; cvta.to.shared.u64 t, %1; cvt.u32.u64 %0, t; }" : "=r"(a) : "l"(p));
    return a;
}
__device__ __forceinline__ void cp16(uint32_t sm, const void* g) {
    asm volatile("cp.async.cg.shared.global [%0], [%1], 16;" :: "r"(sm), "l"(g));
}
__device__ __forceinline__ void cp_commit() {
    asm volatile("cp.async.commit_group;" ::: "memory");
}
template <int N>
__device__ __forceinline__ void cp_wait() {
    asm volatile("cp.async.wait_group %0;" :: "n"(N) : "memory");
}
__device__ __forceinline__ void ldsm_x4(uint32_t* r, uint32_t addr) {
    asm volatile("ldmatrix.sync.aligned.m8n8.x4.shared.b16 {%0,%1,%2,%3}, [%4];"
                 : "=r"(r[0]), "=r"(r[1]), "=r"(r[2]), "=r"(r[3]) : "r"(addr));
}
__device__ __forceinline__ void mma_bf16(float* c, const uint32_t* a, const uint32_t* b) {
    asm volatile("mma.sync.aligned.m16n8k16.row.col.f32.bf16.bf16.f32 "
                 "{%0,%1,%2,%3}, {%4,%5,%6,%7}, {%8,%9}, {%0,%1,%2,%3};"
                 : "+f"(c[0]), "+f"(c[1]), "+f"(c[2]), "+f"(c[3])
                 : "r"(a[0]), "r"(a[1]), "r"(a[2]), "r"(a[3]), "r"(b[0]), "r"(b[1]));
}
__device__ __forceinline__ void split_store(char* sm_hi, char* sm_lo, int off,
                                            float v0, float v1, float v2, float v3) {
    const __nv_bfloat16 h0 = __float2bfloat16(v0), h1 = __float2bfloat16(v1);
    const __nv_bfloat16 h2 = __float2bfloat16(v2), h3 = __float2bfloat16(v3);
    const __nv_bfloat16 l0 = __float2bfloat16(v0 - __bfloat162float(h0));
    const __nv_bfloat16 l1 = __float2bfloat16(v1 - __bfloat162float(h1));
    const __nv_bfloat16 l2 = __float2bfloat16(v2 - __bfloat162float(h2));
    const __nv_bfloat16 l3 = __float2bfloat16(v3 - __bfloat162float(h3));
    ushort4 ph, pl;
    ph.x = __bfloat16_as_ushort(h0); ph.y = __bfloat16_as_ushort(h1);
    ph.z = __bfloat16_as_ushort(h2); ph.w = __bfloat16_as_ushort(h3);
    pl.x = __bfloat16_as_ushort(l0); pl.y = __bfloat16_as_ushort(l1);
    pl.z = __bfloat16_as_ushort(l2); pl.w = __bfloat16_as_ushort(l3);
    *(ushort4*)(sm_hi + off) = ph;
    *(ushort4*)(sm_lo + off) = pl;
}

// ---------------- fused prep: weight transpose/split + zw/ew + coeff init ----
__global__ void k_prep(const float* __restrict__ w_h,
                       const float* __restrict__ z, const float* __restrict__ emb,
                       const float* __restrict__ w_in, const float* __restrict__ b_in,
                       const float* __restrict__ b_out) {
    if (blockIdx.x < 768) {
        __shared__ float t[32][33];
        const int idx = blockIdx.x;
        const int l = idx >> 8;
        const int rem = idx & 255;
        const int k0 = (rem >> 4) * 32, n0 = (rem & 15) * 32;
        const int tx = threadIdx.x & 31, ty = threadIdx.x >> 5;
        const float* W = w_h + (size_t)l * HID_ * HID_;
        for (int i = ty; i < 32; i += 8)
            t[i][tx] = W[(size_t)(k0 + i) * HID_ + n0 + tx];
        __syncthreads();
        for (int i = ty; i < 32; i += 8) {
            const float v = t[tx][i];
            const __nv_bfloat16 hi = __float2bfloat16(v);
            const __nv_bfloat16 lo = __float2bfloat16(v - __bfloat162float(hi));
            g_wthi[l][(size_t)(n0 + i) * HID_ + k0 + tx] = hi;
            g_wtlo[l][(size_t)(n0 + i) * HID_ + k0 + tx] = lo;
        }
    } else {
        __shared__ float vr[E_];
        const int idx2 = blockIdx.x - 768;
        const int dblk = idx2 & 1;
        const int y = idx2 >> 1;
        const bool is_z = (y < B_);
        const int row = is_z ? y : y - B_;
        const float* src = (is_z ? z : emb) + (size_t)row * E_;
        for (int e = threadIdx.x; e < E_; e += blockDim.x) vr[e] = src[e];
        __syncthreads();
        const int d = dblk * 256 + threadIdx.x;
        float acc = is_z ? 0.f : b_in[d];
        #pragma unroll 2
        for (int e = 0; e < E_; e++) acc = fmaf(vr[e], __ldg(w_in + e * HID_ + d), acc);
        if (is_z) g_zw[row * HID_ + d] = acc;
        else      g_ew[row * HID_ + d] = acc;
        if (!is_z && row < 16) {
            const int i = row * HID_ + d;
            g_sinc[i] = b_out[0];
            g_cosc[i] = b_out[1];
        }
    }
}

// ---------------- fused MLP GEMM (CTA 256x128, warp 64x64, KC=64, 2-stage) ----
// One __syncthreads per chunk; stage(c+1) issued AFTER the sync (WAR-safe).
// Term-major MMA ordering: 8 independent MMAs between dependent ones.
template <int MODE>
__global__ void __launch_bounds__(256, 1) k_mma_gemm(int layer, int src, int dst,
                                                     const float* __restrict__ bias,
                                                     const float* __restrict__ w_out) {
    extern __shared__ char smem[];
    const int tid = threadIdx.x;
    const int wid = tid >> 5;
    const int lane = tid & 31;
    const int wm = wid & 3;
    const int wn = wid >> 2;
    const int m0 = blockIdx.y * BM_;
    const int n0 = blockIdx.x * BN_;

    const __nv_bfloat16* __restrict__ Ahi  = g_ahi[src];
    const __nv_bfloat16* __restrict__ Alo  = g_alo[src];
    const __nv_bfloat16* __restrict__ Wthi = g_wthi[layer];
    const __nv_bfloat16* __restrict__ Wtlo = g_wtlo[layer];
    __nv_bfloat16* __restrict__ Dhi = g_ahi[dst];
    __nv_bfloat16* __restrict__ Dlo = g_alo[dst];

    const uint32_t smb = smem_u32(smem);

    auto stage_load = [&](int c) {
        const int k0 = c * KC_;
        const int buf = c & 1;
        char* sb = smem + buf * STAGE_B;
        const uint32_t sbu = smb + buf * STAGE_B;
        if (MODE != 1) {
            #pragma unroll
            for (int i = 0; i < 16; i++) {          // A hi/lo: 4096 cp16
                const int idx = tid + i * 256;
                const int t = idx >> 11;
                const int j = idx & 2047;
                const int r = j >> 3;
                const int c16 = j & 7;
                const uint32_t sm = sbu + (t ? OFF_AL : OFF_AH) + r * ROWB_ + c16 * 16;
                const __nv_bfloat16* gp = (t ? Alo : Ahi) + (size_t)(m0 + r) * HID_ + k0 + c16 * 8;
                cp16(sm, gp);
            }
        } else {
            // A = silu(zw[b] + ew[h]) split hi/lo: 256 rows x 64 k
            #pragma unroll
            for (int i = 0; i < 16; i++) {
                const int idx = tid + i * 256;      // 0..4095 quads
                const int r = idx >> 4;
                const int q = idx & 15;
                const int row = m0 + r;
                const int bb = row >> 7;
                const int hh = row & (NH_ - 1);
                const float4 zv = *(const float4*)(g_zw + bb * HID_ + k0 + q * 4);
                const float4 ev = *(const float4*)(g_ew + hh * HID_ + k0 + q * 4);
                split_store(sb + OFF_AH, sb + OFF_AL, r * ROWB_ + q * 8,
                            silu(zv.x + ev.x), silu(zv.y + ev.y),
                            silu(zv.z + ev.z), silu(zv.w + ev.w));
            }
        }
        #pragma unroll
        for (int i = 0; i < 8; i++) {               // B hi/lo: 2048 cp16
            const int idx = tid + i * 256;
            const int t = idx >> 10;
            const int j = idx & 1023;
            const int r = j >> 3;
            const int c16 = j & 7;
            const uint32_t sm = sbu + (t ? OFF_BL : OFF_BH) + r * ROWB_ + c16 * 16;
            const __nv_bfloat16* gp = (t ? Wtlo : Wthi) + (size_t)(n0 + r) * HID_ + k0 + c16 * 8;
            cp16(sm, gp);
        }
        cp_commit();
    };

    float acc[4][8][4];
    #pragma unroll
    for (int i = 0; i < 4; i++)
        #pragma unroll
        for (int j = 0; j < 8; j++)
            #pragma unroll
            for (int q = 0; q < 4; q++) acc[i][j][q] = 0.f;

    const int arow = wm * 64 + (lane & 15);
    const int acol = (lane >> 4) << 3;
    const int brow = wn * 64 + ((lane >> 4) & 1) * 8 + (lane & 7);
    const int bcol = ((lane >> 3) & 1) * 8;

    stage_load(0);

    for (int c = 0; c < NCH_; c++) {
        cp_wait<0>();
        __syncthreads();
        if (c + 1 < NCH_) stage_load(c + 1);   // after sync: no WAR hazard with c-1 readers

        const uint32_t sbu = smb + (c & 1) * STAGE_B;
        const uint32_t aH = sbu + OFF_AH, aL = sbu + OFF_AL;
        const uint32_t bH = sbu + OFF_BH, bL = sbu + OFF_BL;

        #pragma unroll
        for (int ks = 0; ks < 4; ks++) {
            const int kc = ks * 16;
            uint32_t bh[16], bl[16];
            #pragma unroll
            for (int np = 0; np < 4; np++) {
                const uint32_t bo = (uint32_t)((brow + np * 16) * SPAD_ + bcol + kc) * 2;
                ldsm_x4(bh + np * 4, bH + bo);
                ldsm_x4(bl + np * 4, bL + bo);
            }
            #pragma unroll
            for (int mt = 0; mt < 4; mt++) {
                const uint32_t ao = (uint32_t)((arow + mt * 16) * SPAD_ + acol + kc) * 2;
                uint32_t ah[4], al[4];
                ldsm_x4(ah, aH + ao);
                ldsm_x4(al, aL + ao);
                // term-major: dependent MMAs to the same acc are 8 apart
                #pragma unroll
                for (int nt = 0; nt < 8; nt++) mma_bf16(acc[mt][nt], ah, bh + nt * 2);
                #pragma unroll
                for (int nt = 0; nt < 8; nt++) mma_bf16(acc[mt][nt], ah, bl + nt * 2);
                #pragma unroll
                for (int nt = 0; nt < 8; nt++) mma_bf16(acc[mt][nt], al, bh + nt * 2);
            }
        }
    }

    const int g = lane >> 2;
    const int cpair = (lane & 3) * 2;

    if (MODE != 2) {
        #pragma unroll
        for (int mt = 0; mt < 4; mt++) {
            #pragma unroll
            for (int nt = 0; nt < 8; nt++) {
                const int row = m0 + wm * 64 + mt * 16 + g;
                const int col = n0 + wn * 64 + nt * 8 + cpair;
                const float b0 = __ldg(bias + col);
                const float b1 = __ldg(bias + col + 1);
                #pragma unroll
                for (int half = 0; half < 2; half++) {
                    const int r = row + half * 8;
                    const float v0 = silu(acc[mt][nt][half * 2 + 0] + b0);
                    const float v1 = silu(acc[mt][nt][half * 2 + 1] + b1);
                    const __nv_bfloat16 h0 = __float2bfloat16(v0);
                    const __nv_bfloat16 h1 = __float2bfloat16(v1);
                    const __nv_bfloat16 l0 = __float2bfloat16(v0 - __bfloat162float(h0));
                    const __nv_bfloat16 l1 = __float2bfloat16(v1 - __bfloat162float(h1));
                    __nv_bfloat162 ph, pl;
                    ph.x = h0; ph.y = h1;
                    pl.x = l0; pl.y = l1;
                    *(__nv_bfloat162*)(Dhi + (size_t)r * HID_ + col) = ph;
                    *(__nv_bfloat162*)(Dlo + (size_t)r * HID_ + col) = pl;
                }
            }
        }
    } else {
        #pragma unroll
        for (int mt = 0; mt < 4; mt++) {
            #pragma unroll
            for (int half = 0; half < 2; half++) {
                float s = 0.f, cs = 0.f;
                #pragma unroll
                for (int nt = 0; nt < 8; nt++) {
                    const int col = n0 + wn * 64 + nt * 8 + cpair;
                    const float b0 = __ldg(bias + col);
                    const float b1 = __ldg(bias + col + 1);
                    const float v0 = silu(acc[mt][nt][half * 2 + 0] + b0);
                    const float v1 = silu(acc[mt][nt][half * 2 + 1] + b1);
                    s  = fmaf(v0, __ldg(w_out + 2 * col + 0), s);
                    cs = fmaf(v0, __ldg(w_out + 2 * col + 1), cs);
                    s  = fmaf(v1, __ldg(w_out + 2 * col + 2), s);
                    cs = fmaf(v1, __ldg(w_out + 2 * col + 3), cs);
                }
                s  += __shfl_xor_sync(0xffffffffu, s, 1);
                s  += __shfl_xor_sync(0xffffffffu, s, 2);
                cs += __shfl_xor_sync(0xffffffffu, cs, 1);
                cs += __shfl_xor_sync(0xffffffffu, cs, 2);
                if ((lane & 3) == 0) {
                    const int row = m0 + wm * 64 + mt * 16 + g + half * 8;
                    atomicAdd(&g_sinc[row], s);
                    atomicAdd(&g_cosc[row], cs);
                }
            }
        }
    }
}

// ---------------- synthesis: 2-chain integer-frequency recurrence ----------------
__global__ void k_synth(const float* __restrict__ tx, float* __restrict__ out) {
    __shared__ float sc[NH_], cc[NH_];
    const int b = blockIdx.y;
    if (threadIdx.x < NH_) {
        sc[threadIdx.x] = g_sinc[b * NH_ + threadIdx.x];
        cc[threadIdx.x] = g_cosc[b * NH_ + threadIdx.x];
    }
    __syncthreads();
    const int sI = blockIdx.x * blockDim.x + threadIdx.x;
    const float xv = tx[b * S_ + sI];
    const float th = 6.28318530717958647692f * xv;
    float s1, c1;
    sincosf(th, &s1, &c1);
    const float c2 = c1 * c1 - s1 * s1;
    const float s2 = 2.f * s1 * c1;
    float ca = c1, sa = s1;
    float cb = c2, sb = s2;
    float acc0 = fmaf(cc[0], ca, sc[0] * sa);
    float acc1 = fmaf(cc[1], cb, sc[1] * sb);
    #pragma unroll 4
    for (int i = 1; i < 64; i++) {
        const float can = ca * c2 - sa * s2;
        const float san = sa * c2 + ca * s2;
        ca = can; sa = san;
        const float cbn = cb * c2 - sb * s2;
        const float sbn = sb * c2 + cb * s2;
        cb = cbn; sb = sbn;
        acc0 = fmaf(cc[2 * i], ca, acc0);
        acc0 = fmaf(sc[2 * i], sa, acc0);
        acc1 = fmaf(cc[2 * i + 1], cb, acc1);
        acc1 = fmaf(sc[2 * i + 1], sb, acc1);
    }
    out[b * S_ + sI] = acc0 + acc1;
}

// ---------------- launcher ----------------
extern "C" void kernel_launch(void* const* d_in, const int* in_sizes, int n_in,
                              void* d_out, int out_size) {
    const float* target_x = (const float*)d_in[0];
    const float* z        = (const float*)d_in[1];
    /* d_in[2] = x, unused by the reference */
    const float* emb      = (const float*)d_in[3];
    const float* w_in     = (const float*)d_in[4];
    const float* b_in     = (const float*)d_in[5];
    const float* w_h      = (const float*)d_in[6];
    const float* b_h      = (const float*)d_in[7];
    const float* w_out    = (const float*)d_in[8];
    const float* b_out    = (const float*)d_in[9];
    float* out = (float*)d_out;

    cudaFuncSetAttribute(k_mma_gemm<0>, cudaFuncAttributeMaxDynamicSharedMemorySize, SMEM_DYN);
    cudaFuncSetAttribute(k_mma_gemm<1>, cudaFuncAttributeMaxDynamicSharedMemorySize, SMEM_DYN);
    cudaFuncSetAttribute(k_mma_gemm<2>, cudaFuncAttributeMaxDynamicSharedMemorySize, SMEM_DYN);

    k_prep<<<1152, 256>>>(w_h, z, emb, w_in, b_in, b_out);

    k_mma_gemm<1><<<dim3(HID_ / BN_, M_ / BM_), 256, SMEM_DYN>>>(0, 0, 0, b_h + 0 * HID_, w_out);
    k_mma_gemm<0><<<dim3(HID_ / BN_, M_ / BM_), 256, SMEM_DYN>>>(1, 0, 1, b_h + 1 * HID_, w_out);
    k_mma_gemm<2><<<dim3(HID_ / BN_, M_ / BM_), 256, SMEM_DYN>>>(2, 1, 0, b_h + 2 * HID_, w_out);

    k_synth<<<dim3(S_ / 256, B_), 256>>>(target_x, out);
}

// round 12
// speedup vs baseline: 1.0824x; 1.0824x over previous
#include <cuda_runtime.h>
#include <cuda_bf16.h>
#include <math.h>
#include <stdint.h>

#define B_    64
#define S_    4096
#define E_    266
#define HID_  512
#define NH_   128
#define M_    (B_ * NH_)   /* 8192 rows */
#define KC_   32           /* K chunk */
#define NCH_  (HID_ / KC_) /* 16 chunks */
#define SPAD_ 40           /* padded smem row stride in bf16 */
#define BM_   256          /* CTA tile M */
#define BN_   128          /* CTA tile N */
#define NT_   512          /* threads per CTA: 16 warps, warp grid 4x4, warp tile 64x32 */

#define ROWB_     (SPAD_ * 2)                       /* 80 B */
#define OFF_AH    0
#define OFF_AL    (BM_ * ROWB_)                     /* 20480 */
#define OFF_BH    (2 * BM_ * ROWB_)                 /* 40960 */
#define OFF_BL    (2 * BM_ * ROWB_ + BN_ * ROWB_)   /* 51200 */
#define STAGE_B   (2 * BM_ * ROWB_ + 2 * BN_ * ROWB_) /* 61440 */
#define NSTAGE_   3
#define SMEM_DYN  (NSTAGE_ * STAGE_B)               /* 184320 */

__device__ __align__(16) __nv_bfloat16 g_ahi[2][M_ * HID_];
__device__ __align__(16) __nv_bfloat16 g_alo[2][M_ * HID_];
__device__ __align__(16) __nv_bfloat16 g_wthi[3][HID_ * HID_];
__device__ __align__(16) __nv_bfloat16 g_wtlo[3][HID_ * HID_];
__device__ float g_zw[B_ * HID_];
__device__ float g_ew[NH_ * HID_];
__device__ float g_sinc[M_];
__device__ float g_cosc[M_];

__device__ __forceinline__ float silu(float v) {
    return __fdividef(v, 1.0f + __expf(-v));
}
__device__ __forceinline__ uint32_t smem_u32(const void* p) {
    uint32_t a;
    asm("{ .reg .u64 t; cvta.to.shared.u64 t, %1; cvt.u32.u64 %0, t; }" : "=r"(a) : "l"(p));
    return a;
}
__device__ __forceinline__ void cp16(uint32_t sm, const void* g) {
    asm volatile("cp.async.cg.shared.global [%0], [%1], 16;" :: "r"(sm), "l"(g));
}
__device__ __forceinline__ void cp_commit() {
    asm volatile("cp.async.commit_group;" ::: "memory");
}
template <int N>
__device__ __forceinline__ void cp_wait() {
    asm volatile("cp.async.wait_group %0;" :: "n"(N) : "memory");
}
__device__ __forceinline__ void ldsm_x4(uint32_t* r, uint32_t addr) {
    asm volatile("ldmatrix.sync.aligned.m8n8.x4.shared.b16 {%0,%1,%2,%3}, [%4];"
                 : "=r"(r[0]), "=r"(r[1]), "=r"(r[2]), "=r"(r[3]) : "r"(addr));
}
__device__ __forceinline__ void mma_bf16(float* c, const uint32_t* a, const uint32_t* b) {
    asm volatile("mma.sync.aligned.m16n8k16.row.col.f32.bf16.bf16.f32 "
                 "{%0,%1,%2,%3}, {%4,%5,%6,%7}, {%8,%9}, {%0,%1,%2,%3};"
                 : "+f"(c[0]), "+f"(c[1]), "+f"(c[2]), "+f"(c[3])
                 : "r"(a[0]), "r"(a[1]), "r"(a[2]), "r"(a[3]), "r"(b[0]), "r"(b[1]));
}
__device__ __forceinline__ void split_store(char* sm_hi, char* sm_lo, int off,
                                            float v0, float v1, float v2, float v3) {
    const __nv_bfloat16 h0 = __float2bfloat16(v0), h1 = __float2bfloat16(v1);
    const __nv_bfloat16 h2 = __float2bfloat16(v2), h3 = __float2bfloat16(v3);
    const __nv_bfloat16 l0 = __float2bfloat16(v0 - __bfloat162float(h0));
    const __nv_bfloat16 l1 = __float2bfloat16(v1 - __bfloat162float(h1));
    const __nv_bfloat16 l2 = __float2bfloat16(v2 - __bfloat162float(h2));
    const __nv_bfloat16 l3 = __float2bfloat16(v3 - __bfloat162float(h3));
    ushort4 ph, pl;
    ph.x = __bfloat16_as_ushort(h0); ph.y = __bfloat16_as_ushort(h1);
    ph.z = __bfloat16_as_ushort(h2); ph.w = __bfloat16_as_ushort(h3);
    pl.x = __bfloat16_as_ushort(l0); pl.y = __bfloat16_as_ushort(l1);
    pl.z = __bfloat16_as_ushort(l2); pl.w = __bfloat16_as_ushort(l3);
    *(ushort4*)(sm_hi + off) = ph;
    *(ushort4*)(sm_lo + off) = pl;
}

// ---------------- fused prep: weight transpose/split + zw/ew + coeff init ----
__global__ void k_prep(const float* __restrict__ w_h,
                       const float* __restrict__ z, const float* __restrict__ emb,
                       const float* __restrict__ w_in, const float* __restrict__ b_in,
                       const float* __restrict__ b_out) {
    if (blockIdx.x < 768) {
        __shared__ float t[32][33];
        const int idx = blockIdx.x;
        const int l = idx >> 8;
        const int rem = idx & 255;
        const int k0 = (rem >> 4) * 32, n0 = (rem & 15) * 32;
        const int tx = threadIdx.x & 31, ty = threadIdx.x >> 5;
        const float* W = w_h + (size_t)l * HID_ * HID_;
        for (int i = ty; i < 32; i += 8)
            t[i][tx] = W[(size_t)(k0 + i) * HID_ + n0 + tx];
        __syncthreads();
        for (int i = ty; i < 32; i += 8) {
            const float v = t[tx][i];
            const __nv_bfloat16 hi = __float2bfloat16(v);
            const __nv_bfloat16 lo = __float2bfloat16(v - __bfloat162float(hi));
            g_wthi[l][(size_t)(n0 + i) * HID_ + k0 + tx] = hi;
            g_wtlo[l][(size_t)(n0 + i) * HID_ + k0 + tx] = lo;
        }
    } else {
        __shared__ float vr[E_];
        const int idx2 = blockIdx.x - 768;
        const int dblk = idx2 & 1;
        const int y = idx2 >> 1;
        const bool is_z = (y < B_);
        const int row = is_z ? y : y - B_;
        const float* src = (is_z ? z : emb) + (size_t)row * E_;
        for (int e = threadIdx.x; e < E_; e += blockDim.x) vr[e] = src[e];
        __syncthreads();
        const int d = dblk * 256 + threadIdx.x;
        float acc = is_z ? 0.f : b_in[d];
        #pragma unroll 2
        for (int e = 0; e < E_; e++) acc = fmaf(vr[e], __ldg(w_in + e * HID_ + d), acc);
        if (is_z) g_zw[row * HID_ + d] = acc;
        else      g_ew[row * HID_ + d] = acc;
        if (!is_z && row < 16) {
            const int i = row * HID_ + d;
            g_sinc[i] = b_out[0];
            g_cosc[i] = b_out[1];
        }
    }
}

// ---------------- fused MLP GEMM (CTA 256x128, 16 warps, warp 64x32, 3-stage) --
template <int MODE>
__global__ void __launch_bounds__(NT_, 1) k_mma_gemm(int layer, int src, int dst,
                                                     const float* __restrict__ bias,
                                                     const float* __restrict__ w_out) {
    extern __shared__ char smem[];
    const int tid = threadIdx.x;
    const int wid = tid >> 5;
    const int lane = tid & 31;
    const int wm = wid & 3;        // 4 warp-rows of 64
    const int wn = wid >> 2;       // 4 warp-cols of 32
    const int m0 = blockIdx.y * BM_;
    const int n0 = blockIdx.x * BN_;

    const __nv_bfloat16* __restrict__ Ahi  = g_ahi[src];
    const __nv_bfloat16* __restrict__ Alo  = g_alo[src];
    const __nv_bfloat16* __restrict__ Wthi = g_wthi[layer];
    const __nv_bfloat16* __restrict__ Wtlo = g_wtlo[layer];
    __nv_bfloat16* __restrict__ Dhi = g_ahi[dst];
    __nv_bfloat16* __restrict__ Dlo = g_alo[dst];

    const uint32_t smb = smem_u32(smem);

    auto stage_load = [&](int c) {
        const int k0 = c * KC_;
        const int buf = c % NSTAGE_;
        char* sb = smem + buf * STAGE_B;
        const uint32_t sbu = smb + buf * STAGE_B;
        if (MODE != 1) {
            #pragma unroll
            for (int i = 0; i < 4; i++) {           // A hi/lo: 2048 cp16
                const int idx = tid + i * NT_;
                const int t = idx >> 10;
                const int j = idx & 1023;
                const int r = j >> 2;
                const int c16 = j & 3;
                const uint32_t sm = sbu + (t ? OFF_AL : OFF_AH) + r * ROWB_ + c16 * 16;
                const __nv_bfloat16* gp = (t ? Alo : Ahi) + (size_t)(m0 + r) * HID_ + k0 + c16 * 8;
                cp16(sm, gp);
            }
        } else {
            // A = silu(zw[b] + ew[h]) split hi/lo: 256 rows x 32 k (2048 quads)
            #pragma unroll
            for (int i = 0; i < 4; i++) {
                const int idx = tid + i * NT_;
                const int r = idx >> 3;
                const int q = idx & 7;
                const int row = m0 + r;
                const int bb = row >> 7;
                const int hh = row & (NH_ - 1);
                const float4 zv = *(const float4*)(g_zw + bb * HID_ + k0 + q * 4);
                const float4 ev = *(const float4*)(g_ew + hh * HID_ + k0 + q * 4);
                split_store(sb + OFF_AH, sb + OFF_AL, r * ROWB_ + q * 8,
                            silu(zv.x + ev.x), silu(zv.y + ev.y),
                            silu(zv.z + ev.z), silu(zv.w + ev.w));
            }
        }
        #pragma unroll
        for (int i = 0; i < 2; i++) {               // B hi/lo: 1024 cp16
            const int idx = tid + i * NT_;
            const int t = idx >> 9;
            const int j = idx & 511;
            const int r = j >> 2;
            const int c16 = j & 3;
            const uint32_t sm = sbu + (t ? OFF_BL : OFF_BH) + r * ROWB_ + c16 * 16;
            const __nv_bfloat16* gp = (t ? Wtlo : Wthi) + (size_t)(n0 + r) * HID_ + k0 + c16 * 8;
            cp16(sm, gp);
        }
        cp_commit();
    };

    float acc[4][4][4];
    #pragma unroll
    for (int i = 0; i < 4; i++)
        #pragma unroll
        for (int j = 0; j < 4; j++)
            #pragma unroll
            for (int q = 0; q < 4; q++) acc[i][j][q] = 0.f;

    const int arow = wm * 64 + (lane & 15);
    const int acol = (lane >> 4) << 3;
    const int brow = wn * 32 + ((lane >> 4) & 1) * 8 + (lane & 7);
    const int bcol = ((lane >> 3) & 1) * 8;

    stage_load(0);

    for (int c = 0; c < NCH_; c++) {
        if (c + 1 < NCH_) {
            stage_load(c + 1);
            cp_wait<1>();
        } else {
            cp_wait<0>();
        }
        __syncthreads();   // single barrier per chunk (3-stage: no WAR hazard)

        const uint32_t sbu = smb + (c % NSTAGE_) * STAGE_B;
        const uint32_t aH = sbu + OFF_AH, aL = sbu + OFF_AL;
        const uint32_t bH = sbu + OFF_BH, bL = sbu + OFF_BL;

        #pragma unroll
        for (int ks = 0; ks < 2; ks++) {
            const int kc = ks * 16;
            uint32_t bh[8], bl[8];
            #pragma unroll
            for (int np = 0; np < 2; np++) {
                const uint32_t bo = (uint32_t)((brow + np * 16) * SPAD_ + bcol + kc) * 2;
                ldsm_x4(bh + np * 4, bH + bo);
                ldsm_x4(bl + np * 4, bL + bo);
            }
            #pragma unroll
            for (int mt = 0; mt < 4; mt++) {
                const uint32_t ao = (uint32_t)((arow + mt * 16) * SPAD_ + acol + kc) * 2;
                uint32_t ah[4], al[4];
                ldsm_x4(ah, aH + ao);
                ldsm_x4(al, aL + ao);
                #pragma unroll
                for (int nt = 0; nt < 4; nt++) mma_bf16(acc[mt][nt], ah, bh + nt * 2);
                #pragma unroll
                for (int nt = 0; nt < 4; nt++) mma_bf16(acc[mt][nt], ah, bl + nt * 2);
                #pragma unroll
                for (int nt = 0; nt < 4; nt++) mma_bf16(acc[mt][nt], al, bh + nt * 2);
            }
        }
    }

    const int g = lane >> 2;
    const int cpair = (lane & 3) * 2;

    if (MODE != 2) {
        #pragma unroll
        for (int mt = 0; mt < 4; mt++) {
            #pragma unroll
            for (int nt = 0; nt < 4; nt++) {
                const int row = m0 + wm * 64 + mt * 16 + g;
                const int col = n0 + wn * 32 + nt * 8 + cpair;
                const float b0 = __ldg(bias + col);
                const float b1 = __ldg(bias + col + 1);
                #pragma unroll
                for (int half = 0; half < 2; half++) {
                    const int r = row + half * 8;
                    const float v0 = silu(acc[mt][nt][half * 2 + 0] + b0);
                    const float v1 = silu(acc[mt][nt][half * 2 + 1] + b1);
                    const __nv_bfloat16 h0 = __float2bfloat16(v0);
                    const __nv_bfloat16 h1 = __float2bfloat16(v1);
                    const __nv_bfloat16 l0 = __float2bfloat16(v0 - __bfloat162float(h0));
                    const __nv_bfloat16 l1 = __float2bfloat16(v1 - __bfloat162float(h1));
                    __nv_bfloat162 ph, pl;
                    ph.x = h0; ph.y = h1;
                    pl.x = l0; pl.y = l1;
                    *(__nv_bfloat162*)(Dhi + (size_t)r * HID_ + col) = ph;
                    *(__nv_bfloat162*)(Dlo + (size_t)r * HID_ + col) = pl;
                }
            }
        }
    } else {
        #pragma unroll
        for (int mt = 0; mt < 4; mt++) {
            #pragma unroll
            for (int half = 0; half < 2; half++) {
                float s = 0.f, cs = 0.f;
                #pragma unroll
                for (int nt = 0; nt < 4; nt++) {
                    const int col = n0 + wn * 32 + nt * 8 + cpair;
                    const float b0 = __ldg(bias + col);
                    const float b1 = __ldg(bias + col + 1);
                    const float v0 = silu(acc[mt][nt][half * 2 + 0] + b0);
                    const float v1 = silu(acc[mt][nt][half * 2 + 1] + b1);
                    s  = fmaf(v0, __ldg(w_out + 2 * col + 0), s);
                    cs = fmaf(v0, __ldg(w_out + 2 * col + 1), cs);
                    s  = fmaf(v1, __ldg(w_out + 2 * col + 2), s);
                    cs = fmaf(v1, __ldg(w_out + 2 * col + 3), cs);
                }
                s  += __shfl_xor_sync(0xffffffffu, s, 1);
                s  += __shfl_xor_sync(0xffffffffu, s, 2);
                cs += __shfl_xor_sync(0xffffffffu, cs, 1);
                cs += __shfl_xor_sync(0xffffffffu, cs, 2);
                if ((lane & 3) == 0) {
                    const int row = m0 + wm * 64 + mt * 16 + g + half * 8;
                    atomicAdd(&g_sinc[row], s);
                    atomicAdd(&g_cosc[row], cs);
                }
            }
        }
    }
}

// ---------------- synthesis: 2-chain integer-frequency recurrence ----------------
__global__ void k_synth(const float* __restrict__ tx, float* __restrict__ out) {
    __shared__ float sc[NH_], cc[NH_];
    const int b = blockIdx.y;
    if (threadIdx.x < NH_) {
        sc[threadIdx.x] = g_sinc[b * NH_ + threadIdx.x];
        cc[threadIdx.x] = g_cosc[b * NH_ + threadIdx.x];
    }
    __syncthreads();
    const int sI = blockIdx.x * blockDim.x + threadIdx.x;
    const float xv = tx[b * S_ + sI];
    const float th = 6.28318530717958647692f * xv;
    float s1, c1;
    sincosf(th, &s1, &c1);
    const float c2 = c1 * c1 - s1 * s1;
    const float s2 = 2.f * s1 * c1;
    float ca = c1, sa = s1;
    float cb = c2, sb = s2;
    float acc0 = fmaf(cc[0], ca, sc[0] * sa);
    float acc1 = fmaf(cc[1], cb, sc[1] * sb);
    #pragma unroll 4
    for (int i = 1; i < 64; i++) {
        const float can = ca * c2 - sa * s2;
        const float san = sa * c2 + ca * s2;
        ca = can; sa = san;
        const float cbn = cb * c2 - sb * s2;
        const float sbn = sb * c2 + cb * s2;
        cb = cbn; sb = sbn;
        acc0 = fmaf(cc[2 * i], ca, acc0);
        acc0 = fmaf(sc[2 * i], sa, acc0);
        acc1 = fmaf(cc[2 * i + 1], cb, acc1);
        acc1 = fmaf(sc[2 * i + 1], sb, acc1);
    }
    out[b * S_ + sI] = acc0 + acc1;
}

// ---------------- launcher ----------------
extern "C" void kernel_launch(void* const* d_in, const int* in_sizes, int n_in,
                              void* d_out, int out_size) {
    const float* target_x = (const float*)d_in[0];
    const float* z        = (const float*)d_in[1];
    /* d_in[2] = x, unused by the reference */
    const float* emb      = (const float*)d_in[3];
    const float* w_in     = (const float*)d_in[4];
    const float* b_in     = (const float*)d_in[5];
    const float* w_h      = (const float*)d_in[6];
    const float* b_h      = (const float*)d_in[7];
    const float* w_out    = (const float*)d_in[8];
    const float* b_out    = (const float*)d_in[9];
    float* out = (float*)d_out;

    cudaFuncSetAttribute(k_mma_gemm<0>, cudaFuncAttributeMaxDynamicSharedMemorySize, SMEM_DYN);
    cudaFuncSetAttribute(k_mma_gemm<1>, cudaFuncAttributeMaxDynamicSharedMemorySize, SMEM_DYN);
    cudaFuncSetAttribute(k_mma_gemm<2>, cudaFuncAttributeMaxDynamicSharedMemorySize, SMEM_DYN);

    k_prep<<<1152, 256>>>(w_h, z, emb, w_in, b_in, b_out);

    k_mma_gemm<1><<<dim3(HID_ / BN_, M_ / BM_), NT_, SMEM_DYN>>>(0, 0, 0, b_h + 0 * HID_, w_out);
    k_mma_gemm<0><<<dim3(HID_ / BN_, M_ / BM_), NT_, SMEM_DYN>>>(1, 0, 1, b_h + 1 * HID_, w_out);
    k_mma_gemm<2><<<dim3(HID_ / BN_, M_ / BM_), NT_, SMEM_DYN>>>(2, 1, 0, b_h + 2 * HID_, w_out);

    k_synth<<<dim3(S_ / 256, B_), 256>>>(target_x, out);
}